// round 1
// baseline (speedup 1.0000x reference)
#include <cuda_runtime.h>
#include <cstdint>

// Problem constants (fixed shapes per setup_inputs)
#define NN     100000
#define NE     1600000
#define H      64
#define SCD    6
#define ED     16
#define NL     2
#define MSGIN  156   // 2*H + 2*SCD + ED
#define NG     128

// Scratch (device globals; no allocation allowed)
__device__ float g_h[NN * H];
__device__ float g_P[NN * H];
__device__ float g_Q[NN * H];
__device__ float g_S[NN * H];
__device__ float g_cnt[NN];

__device__ __forceinline__ void red_add_v2(float* p, float a, float b) {
    asm volatile("red.global.add.v2.f32 [%0], {%1, %2};"
                 :: "l"(p), "f"(a), "f"(b) : "memory");
}

// ---------------------------------------------------------------------------
// Zero g_cnt and the graph_feature region of the output
// ---------------------------------------------------------------------------
__global__ void k_zero(float* __restrict__ out) {
    int i = blockIdx.x * blockDim.x + threadIdx.x;
    if (i < NN) g_cnt[i] = 0.f;
    if (i < NG * H) out[i] = 0.f;
}

// ---------------------------------------------------------------------------
// cnt[n] = sum of edge_weight over edges with dst == n  (layer-invariant)
// ---------------------------------------------------------------------------
__global__ void k_cnt(const int* __restrict__ el, const float* __restrict__ ew) {
    int e = blockIdx.x * blockDim.x + threadIdx.x;
    if (e < NE) atomicAdd(&g_cnt[el[2 * e + 1]], ew[e]);
}

// ---------------------------------------------------------------------------
// h0 = x @ lin_w + lin_b   (warp-per-node, weights in smem)
// ---------------------------------------------------------------------------
__global__ void k_h0(const float* __restrict__ x, const float* __restrict__ w,
                     const float* __restrict__ b) {
    __shared__ float sW[H * H];
    __shared__ float sB[H];
    __shared__ float sbuf[8][H];
    for (int i = threadIdx.x; i < H * H; i += blockDim.x) sW[i] = w[i];
    for (int i = threadIdx.x; i < H; i += blockDim.x) sB[i] = b[i];
    __syncthreads();

    int wid = threadIdx.x >> 5, lane = threadIdx.x & 31;
    int nwarps = (blockDim.x >> 5) * gridDim.x;
    int gw = blockIdx.x * (blockDim.x >> 5) + wid;
    for (int n = gw; n < NN; n += nwarps) {
        float2 xv = *(const float2*)&x[n * H + 2 * lane];
        sbuf[wid][2 * lane] = xv.x;
        sbuf[wid][2 * lane + 1] = xv.y;
        __syncwarp();
        float a0 = sB[2 * lane], a1 = sB[2 * lane + 1];
#pragma unroll 16
        for (int i = 0; i < H; i++) {
            float xi = sbuf[wid][i];
            float2 wv = *(const float2*)&sW[i * H + 2 * lane];
            a0 = fmaf(xi, wv.x, a0);
            a1 = fmaf(xi, wv.y, a1);
        }
        *(float2*)&g_h[n * H + 2 * lane] = make_float2(a0, a1);
        __syncwarp();
    }
}

// ---------------------------------------------------------------------------
// Per-layer node precompute:
//   P = h @ Wa + scf @ Wc + b1   (src-role term, b1 folded in)
//   Q = h @ Wb + scf @ Wd        (dst-role term)
// Also zeroes g_S for the coming edge pass.
// W1 row blocks: [0:64)=Wa(h_src), [64:128)=Wb(h_dst), [128:134)=Wc(sc_src),
//                [134:140)=Wd(sc_dst), [140:156)=We(edge_feature)
// ---------------------------------------------------------------------------
__global__ void k_pq(const float* __restrict__ w1, const float* __restrict__ b1,
                     const int* __restrict__ nstruct) {
    __shared__ float sWP[(H + SCD) * H];
    __shared__ float sWQ[(H + SCD) * H];
    __shared__ float sB1[H];
    __shared__ float sbuf[8][72];
    for (int i = threadIdx.x; i < H * H; i += blockDim.x) {
        sWP[i] = w1[i];              // Wa
        sWQ[i] = w1[H * H + i];      // Wb
    }
    for (int i = threadIdx.x; i < SCD * H; i += blockDim.x) {
        sWP[H * H + i] = w1[2 * H * H + i];           // Wc
        sWQ[H * H + i] = w1[2 * H * H + SCD * H + i]; // Wd
    }
    for (int i = threadIdx.x; i < H; i += blockDim.x) sB1[i] = b1[i];
    __syncthreads();

    int wid = threadIdx.x >> 5, lane = threadIdx.x & 31;
    int nwarps = (blockDim.x >> 5) * gridDim.x;
    int gw = blockIdx.x * (blockDim.x >> 5) + wid;
    for (int n = gw; n < NN; n += nwarps) {
        float2 hv = *(const float2*)&g_h[n * H + 2 * lane];
        sbuf[wid][2 * lane] = hv.x;
        sbuf[wid][2 * lane + 1] = hv.y;
        if (lane < SCD) sbuf[wid][H + lane] = (float)nstruct[n * SCD + lane];
        __syncwarp();
        float p0 = sB1[2 * lane], p1 = sB1[2 * lane + 1];
        float q0 = 0.f, q1 = 0.f;
#pragma unroll 10
        for (int i = 0; i < H + SCD; i++) {
            float v = sbuf[wid][i];
            float2 wp = *(const float2*)&sWP[i * H + 2 * lane];
            float2 wq = *(const float2*)&sWQ[i * H + 2 * lane];
            p0 = fmaf(v, wp.x, p0);
            p1 = fmaf(v, wp.y, p1);
            q0 = fmaf(v, wq.x, q0);
            q1 = fmaf(v, wq.y, q1);
        }
        *(float2*)&g_P[n * H + 2 * lane] = make_float2(p0, p1);
        *(float2*)&g_Q[n * H + 2 * lane] = make_float2(q0, q1);
        *(float2*)&g_S[n * H + 2 * lane] = make_float2(0.f, 0.f);
        __syncwarp();
    }
}

// ---------------------------------------------------------------------------
// Edge pass (warp-per-edge, grid-stride):
//   t = relu(P[src] + Q[dst] + ef @ We)   (b1 already inside P)
//   g_S[dst] += edge_weight * t           (vector f32 reductions)
// ---------------------------------------------------------------------------
__global__ void k_edge(const float* __restrict__ We_g, const int* __restrict__ el,
                       const float* __restrict__ ef, const float* __restrict__ ew) {
    __shared__ float sWe[ED * H];
    for (int i = threadIdx.x; i < ED * H; i += blockDim.x) sWe[i] = We_g[i];
    __syncthreads();

    int wid = threadIdx.x >> 5, lane = threadIdx.x & 31;
    int nwarps = (blockDim.x >> 5) * gridDim.x;
    int gw = blockIdx.x * (blockDim.x >> 5) + wid;
    for (int e = gw; e < NE; e += nwarps) {
        int2 sd = ((const int2*)el)[e];       // broadcast load
        float w = ew[e];                      // broadcast load
        float myef = (lane < ED) ? ef[e * ED + lane] : 0.f;
        float a0 = 0.f, a1 = 0.f;
#pragma unroll
        for (int i = 0; i < ED; i++) {
            float v = __shfl_sync(0xffffffffu, myef, i);
            float2 wv = *(const float2*)&sWe[i * H + 2 * lane];
            a0 = fmaf(v, wv.x, a0);
            a1 = fmaf(v, wv.y, a1);
        }
        float2 p = *(const float2*)&g_P[(long)sd.x * H + 2 * lane];
        float2 q = *(const float2*)&g_Q[(long)sd.y * H + 2 * lane];
        float v0 = fmaxf(p.x + q.x + a0, 0.f) * w;
        float v1 = fmaxf(p.y + q.y + a1, 0.f) * w;
        red_add_v2(&g_S[(long)sd.y * H + 2 * lane], v0, v1);
    }
}

// ---------------------------------------------------------------------------
// Per-layer node update:
//   upd = S @ W2 + cnt * b2
//   t   = relu([h, upd] @ U1 + ub1)
//   h   = relu(t @ U2 + ub2)
// ---------------------------------------------------------------------------
__global__ void k_upd(const float* __restrict__ w2, const float* __restrict__ b2,
                      const float* __restrict__ u1, const float* __restrict__ ub1,
                      const float* __restrict__ u2, const float* __restrict__ ub2) {
    extern __shared__ float sm[];
    float* sW2 = sm;               // 64*64
    float* sU1 = sm + 4096;        // 128*64
    float* sU2 = sm + 12288;       // 64*64
    float* sB2 = sm + 16384;       // 64
    float* sUB1 = sm + 16448;      // 64
    float* sUB2 = sm + 16512;      // 64
    float* sbuf = sm + 16576;      // 8 * 128

    for (int i = threadIdx.x; i < H * H; i += blockDim.x) { sW2[i] = w2[i]; sU2[i] = u2[i]; }
    for (int i = threadIdx.x; i < 2 * H * H; i += blockDim.x) sU1[i] = u1[i];
    for (int i = threadIdx.x; i < H; i += blockDim.x) {
        sB2[i] = b2[i]; sUB1[i] = ub1[i]; sUB2[i] = ub2[i];
    }
    __syncthreads();

    int wid = threadIdx.x >> 5, lane = threadIdx.x & 31;
    float* buf = sbuf + wid * 128;
    int nwarps = (blockDim.x >> 5) * gridDim.x;
    int gw = blockIdx.x * (blockDim.x >> 5) + wid;
    for (int n = gw; n < NN; n += nwarps) {
        // phase 1: upd = S @ W2 + cnt*b2
        float2 sv = *(const float2*)&g_S[n * H + 2 * lane];
        buf[2 * lane] = sv.x;
        buf[2 * lane + 1] = sv.y;
        __syncwarp();
        float cnt = g_cnt[n];
        float u0 = cnt * sB2[2 * lane], uv1 = cnt * sB2[2 * lane + 1];
#pragma unroll 16
        for (int i = 0; i < H; i++) {
            float v = buf[i];
            float2 wv = *(const float2*)&sW2[i * H + 2 * lane];
            u0 = fmaf(v, wv.x, u0);
            uv1 = fmaf(v, wv.y, uv1);
        }
        __syncwarp();
        // phase 2: t = relu([h, upd] @ U1 + ub1)
        float2 hv = *(const float2*)&g_h[n * H + 2 * lane];
        buf[2 * lane] = hv.x;
        buf[2 * lane + 1] = hv.y;
        buf[H + 2 * lane] = u0;
        buf[H + 2 * lane + 1] = uv1;
        __syncwarp();
        float t0 = sUB1[2 * lane], t1 = sUB1[2 * lane + 1];
#pragma unroll 16
        for (int i = 0; i < 2 * H; i++) {
            float v = buf[i];
            float2 wv = *(const float2*)&sU1[i * H + 2 * lane];
            t0 = fmaf(v, wv.x, t0);
            t1 = fmaf(v, wv.y, t1);
        }
        t0 = fmaxf(t0, 0.f);
        t1 = fmaxf(t1, 0.f);
        __syncwarp();
        // phase 3: h = relu(t @ U2 + ub2)
        buf[2 * lane] = t0;
        buf[2 * lane + 1] = t1;
        __syncwarp();
        float z0 = sUB2[2 * lane], z1 = sUB2[2 * lane + 1];
#pragma unroll 16
        for (int i = 0; i < H; i++) {
            float v = buf[i];
            float2 wv = *(const float2*)&sU2[i * H + 2 * lane];
            z0 = fmaf(v, wv.x, z0);
            z1 = fmaf(v, wv.y, z1);
        }
        *(float2*)&g_h[n * H + 2 * lane] = make_float2(fmaxf(z0, 0.f), fmaxf(z1, 0.f));
        __syncwarp();
    }
}

// ---------------------------------------------------------------------------
// Final: graph_feature = segment_sum(h, node2graph); copy node_feature
// Output layout: [graph_feature (128*64), node_feature (100000*64)]
// ---------------------------------------------------------------------------
__global__ void k_final(const int* __restrict__ n2g, float* __restrict__ out) {
    int wid = threadIdx.x >> 5, lane = threadIdx.x & 31;
    int nwarps = (blockDim.x >> 5) * gridDim.x;
    int gw = blockIdx.x * (blockDim.x >> 5) + wid;
    for (int n = gw; n < NN; n += nwarps) {
        int g = n2g[n];
        float2 hv = *(const float2*)&g_h[n * H + 2 * lane];
        red_add_v2(&out[g * H + 2 * lane], hv.x, hv.y);
        *(float2*)&out[NG * H + n * H + 2 * lane] = hv;
    }
}

// ---------------------------------------------------------------------------
// Launch. Input order per metadata:
// 0 x, 1 edge_list, 2 node_struct, 3 edge_feature, 4 edge_weight,
// 5 node2graph, 6 num_graphs, 7 lin_w, 8 lin_b, 9 msg_w1, 10 msg_b1,
// 11 msg_w2, 12 msg_b2, 13 upd_w1, 14 upd_b1, 15 upd_w2, 16 upd_b2
// ---------------------------------------------------------------------------
extern "C" void kernel_launch(void* const* d_in, const int* in_sizes, int n_in,
                              void* d_out, int out_size) {
    const float* x        = (const float*)d_in[0];
    const int*   el       = (const int*)d_in[1];
    const int*   nstruct  = (const int*)d_in[2];
    const float* ef       = (const float*)d_in[3];
    const float* ew       = (const float*)d_in[4];
    const int*   n2g      = (const int*)d_in[5];
    const float* lin_w    = (const float*)d_in[7];
    const float* lin_b    = (const float*)d_in[8];
    const float* msg_w1   = (const float*)d_in[9];
    const float* msg_b1   = (const float*)d_in[10];
    const float* msg_w2   = (const float*)d_in[11];
    const float* msg_b2   = (const float*)d_in[12];
    const float* upd_w1   = (const float*)d_in[13];
    const float* upd_b1   = (const float*)d_in[14];
    const float* upd_w2   = (const float*)d_in[15];
    const float* upd_b2   = (const float*)d_in[16];
    float* out = (float*)d_out;

    static const size_t UPD_SMEM = (16576 + 8 * 128) * sizeof(float);
    cudaFuncSetAttribute(k_upd, cudaFuncAttributeMaxDynamicSharedMemorySize,
                         (int)UPD_SMEM);

    const int TPB = 256;
    const int NODE_BLOCKS = 1184;   // 148 SMs * 8
    const int EDGE_BLOCKS = 4096;

    k_zero<<<(NN + TPB - 1) / TPB, TPB>>>(out);
    k_cnt<<<(NE + TPB - 1) / TPB, TPB>>>(el, ew);
    k_h0<<<NODE_BLOCKS, TPB>>>(x, lin_w, lin_b);

    for (int l = 0; l < NL; l++) {
        const float* w1 = msg_w1 + (size_t)l * MSGIN * H;
        k_pq<<<NODE_BLOCKS, TPB>>>(w1, msg_b1 + l * H, nstruct);
        k_edge<<<EDGE_BLOCKS, TPB>>>(w1 + (2 * H + 2 * SCD) * H, el, ef, ew);
        k_upd<<<NODE_BLOCKS, TPB, UPD_SMEM>>>(
            msg_w2 + (size_t)l * H * H, msg_b2 + l * H,
            upd_w1 + (size_t)l * 2 * H * H, upd_b1 + l * H,
            upd_w2 + (size_t)l * H * H, upd_b2 + l * H);
    }

    k_final<<<NODE_BLOCKS, TPB>>>(n2g, out);
}

// round 2
// speedup vs baseline: 1.6612x; 1.6612x over previous
#include <cuda_runtime.h>
#include <cstdint>

#define NN     100000
#define NE     1600000
#define H      64
#define SCD    6
#define ED     16
#define NL     2
#define MSGIN  156
#define NG     128

__device__ float g_h[NN * H];
__device__ float g_P[NN * H];
__device__ float g_Q[NN * H];
__device__ float g_S[NN * H];
__device__ float g_cnt[NN];

__device__ __forceinline__ void red_add_v4(float* p, float a, float b, float c, float d) {
    asm volatile("red.global.add.v4.f32 [%0], {%1, %2, %3, %4};"
                 :: "l"(p), "f"(a), "f"(b), "f"(c), "f"(d) : "memory");
}
__device__ __forceinline__ void red_add_v2(float* p, float a, float b) {
    asm volatile("red.global.add.v2.f32 [%0], {%1, %2};"
                 :: "l"(p), "f"(a), "f"(b) : "memory");
}

// ---------------------------------------------------------------------------
__global__ void k_zero(float* __restrict__ out) {
    int i = blockIdx.x * blockDim.x + threadIdx.x;
    if (i < NN) g_cnt[i] = 0.f;
    if (i < NG * H) out[i] = 0.f;
}

__global__ void k_cnt(const int* __restrict__ el, const float* __restrict__ ew) {
    int e = blockIdx.x * blockDim.x + threadIdx.x;
    if (e < NE) atomicAdd(&g_cnt[el[2 * e + 1]], ew[e]);
}

// ---------------------------------------------------------------------------
// h0 = x @ lin_w + lin_b   — 4 nodes per warp, register-blocked
// ---------------------------------------------------------------------------
__global__ void k_h0(const float* __restrict__ x, const float* __restrict__ w,
                     const float* __restrict__ b) {
    __shared__ float sW[H * H];
    __shared__ float sB[H];
    __shared__ float sin[8][4][H];
    for (int i = threadIdx.x; i < H * H; i += blockDim.x) sW[i] = w[i];
    for (int i = threadIdx.x; i < H; i += blockDim.x) sB[i] = b[i];
    __syncthreads();

    int wid = threadIdx.x >> 5, lane = threadIdx.x & 31;
    int nwarps = (blockDim.x >> 5) * gridDim.x;
    int gw = blockIdx.x * (blockDim.x >> 5) + wid;
    for (int t = gw; t < NN / 4; t += nwarps) {
        int base = t * 4;
#pragma unroll
        for (int j = 0; j < 4; j++) {
            float2 xv = *(const float2*)&x[(base + j) * H + 2 * lane];
            sin[wid][j][2 * lane] = xv.x;
            sin[wid][j][2 * lane + 1] = xv.y;
        }
        __syncwarp();
        float b0 = sB[2 * lane], b1v = sB[2 * lane + 1];
        float a0[4], a1[4];
#pragma unroll
        for (int j = 0; j < 4; j++) { a0[j] = b0; a1[j] = b1v; }
#pragma unroll 8
        for (int i = 0; i < H; i++) {
            float2 wv = *(const float2*)&sW[i * H + 2 * lane];
#pragma unroll
            for (int j = 0; j < 4; j++) {
                float v = sin[wid][j][i];
                a0[j] = fmaf(v, wv.x, a0[j]);
                a1[j] = fmaf(v, wv.y, a1[j]);
            }
        }
#pragma unroll
        for (int j = 0; j < 4; j++)
            *(float2*)&g_h[(base + j) * H + 2 * lane] = make_float2(a0[j], a1[j]);
        __syncwarp();
    }
}

// ---------------------------------------------------------------------------
// P = h@Wa + sc@Wc + b1 ; Q = h@Wb + sc@Wd ; zero S  — 4 nodes per warp
// ---------------------------------------------------------------------------
__global__ void k_pq(const float* __restrict__ w1, const float* __restrict__ b1,
                     const int* __restrict__ nstruct) {
    __shared__ float sWP[(H + SCD) * H];
    __shared__ float sWQ[(H + SCD) * H];
    __shared__ float sB1[H];
    __shared__ float sin[8][4][H + SCD + 2];
    for (int i = threadIdx.x; i < H * H; i += blockDim.x) {
        sWP[i] = w1[i];
        sWQ[i] = w1[H * H + i];
    }
    for (int i = threadIdx.x; i < SCD * H; i += blockDim.x) {
        sWP[H * H + i] = w1[2 * H * H + i];
        sWQ[H * H + i] = w1[2 * H * H + SCD * H + i];
    }
    for (int i = threadIdx.x; i < H; i += blockDim.x) sB1[i] = b1[i];
    __syncthreads();

    int wid = threadIdx.x >> 5, lane = threadIdx.x & 31;
    int nwarps = (blockDim.x >> 5) * gridDim.x;
    int gw = blockIdx.x * (blockDim.x >> 5) + wid;
    for (int t = gw; t < NN / 4; t += nwarps) {
        int base = t * 4;
#pragma unroll
        for (int j = 0; j < 4; j++) {
            int n = base + j;
            float2 hv = *(const float2*)&g_h[n * H + 2 * lane];
            sin[wid][j][2 * lane] = hv.x;
            sin[wid][j][2 * lane + 1] = hv.y;
            if (lane < SCD) sin[wid][j][H + lane] = (float)nstruct[n * SCD + lane];
        }
        __syncwarp();
        float pb0 = sB1[2 * lane], pb1 = sB1[2 * lane + 1];
        float p0[4], p1[4], q0[4], q1[4];
#pragma unroll
        for (int j = 0; j < 4; j++) { p0[j] = pb0; p1[j] = pb1; q0[j] = 0.f; q1[j] = 0.f; }
#pragma unroll 10
        for (int i = 0; i < H + SCD; i++) {
            float2 wp = *(const float2*)&sWP[i * H + 2 * lane];
            float2 wq = *(const float2*)&sWQ[i * H + 2 * lane];
#pragma unroll
            for (int j = 0; j < 4; j++) {
                float v = sin[wid][j][i];
                p0[j] = fmaf(v, wp.x, p0[j]);
                p1[j] = fmaf(v, wp.y, p1[j]);
                q0[j] = fmaf(v, wq.x, q0[j]);
                q1[j] = fmaf(v, wq.y, q1[j]);
            }
        }
#pragma unroll
        for (int j = 0; j < 4; j++) {
            int n = base + j;
            *(float2*)&g_P[n * H + 2 * lane] = make_float2(p0[j], p1[j]);
            *(float2*)&g_Q[n * H + 2 * lane] = make_float2(q0[j], q1[j]);
            *(float2*)&g_S[n * H + 2 * lane] = make_float2(0.f, 0.f);
        }
        __syncwarp();
    }
}

// ---------------------------------------------------------------------------
// Edge pass: half-warp per edge (2 edges/warp), float4 gathers, red.v4
//   t = relu(P[src] + Q[dst] + ef @ We) ; S[dst] += ew * t
// ---------------------------------------------------------------------------
__global__ void k_edge(const float* __restrict__ We_g, const int* __restrict__ el,
                       const float* __restrict__ ef, const float* __restrict__ ew) {
    __shared__ float sWe[ED * H];
    for (int i = threadIdx.x; i < ED * H; i += blockDim.x) sWe[i] = We_g[i];
    __syncthreads();

    int wid = threadIdx.x >> 5, lane = threadIdx.x & 31;
    int half = lane >> 4, sl = lane & 15;
    int nwarps = (blockDim.x >> 5) * gridDim.x;
    int gw = blockIdx.x * (blockDim.x >> 5) + wid;
    const float4* P4 = (const float4*)g_P;
    const float4* Q4 = (const float4*)g_Q;
    const float4* sWe4 = (const float4*)sWe;
    for (int t = gw; t < NE / 2; t += nwarps) {
        int e = 2 * t + half;
        int2 sd = ((const int2*)el)[e];
        float w = ew[e];
        float myef = ef[e * ED + sl];
        float a0 = 0.f, a1 = 0.f, a2 = 0.f, a3 = 0.f;
#pragma unroll
        for (int i = 0; i < ED; i++) {
            float v = __shfl_sync(0xffffffffu, myef, i, 16);
            float4 wv = sWe4[i * 16 + sl];
            a0 = fmaf(v, wv.x, a0);
            a1 = fmaf(v, wv.y, a1);
            a2 = fmaf(v, wv.z, a2);
            a3 = fmaf(v, wv.w, a3);
        }
        float4 p = P4[(long)sd.x * 16 + sl];
        float4 q = Q4[(long)sd.y * 16 + sl];
        float v0 = fmaxf(p.x + q.x + a0, 0.f) * w;
        float v1 = fmaxf(p.y + q.y + a1, 0.f) * w;
        float v2 = fmaxf(p.z + q.z + a2, 0.f) * w;
        float v3 = fmaxf(p.w + q.w + a3, 0.f) * w;
        red_add_v4(&g_S[(long)sd.y * H + 4 * sl], v0, v1, v2, v3);
    }
}

// ---------------------------------------------------------------------------
// upd = S@W2 + cnt*b2 ; t = relu([h,upd]@U1+ub1) ; h = relu(t@U2+ub2)
// 4 nodes per warp, register-blocked
// ---------------------------------------------------------------------------
__global__ void k_upd(const float* __restrict__ w2, const float* __restrict__ b2,
                      const float* __restrict__ u1, const float* __restrict__ ub1,
                      const float* __restrict__ u2, const float* __restrict__ ub2) {
    extern __shared__ float sm[];
    float* sW2 = sm;               // 4096
    float* sU1 = sm + 4096;        // 8192
    float* sU2 = sm + 12288;       // 4096
    float* sB2 = sm + 16384;       // 64
    float* sUB1 = sm + 16448;      // 64
    float* sUB2 = sm + 16512;      // 64
    float* sbuf = sm + 16576;      // 8 warps * 4 nodes * 128

    for (int i = threadIdx.x; i < H * H; i += blockDim.x) { sW2[i] = w2[i]; sU2[i] = u2[i]; }
    for (int i = threadIdx.x; i < 2 * H * H; i += blockDim.x) sU1[i] = u1[i];
    for (int i = threadIdx.x; i < H; i += blockDim.x) {
        sB2[i] = b2[i]; sUB1[i] = ub1[i]; sUB2[i] = ub2[i];
    }
    __syncthreads();

    int wid = threadIdx.x >> 5, lane = threadIdx.x & 31;
    float* buf = sbuf + wid * 512;  // [4][128]
    int nwarps = (blockDim.x >> 5) * gridDim.x;
    int gw = blockIdx.x * (blockDim.x >> 5) + wid;
    for (int t = gw; t < NN / 4; t += nwarps) {
        int base = t * 4;
        // phase 1: upd = S @ W2 + cnt*b2
        float cnt[4];
#pragma unroll
        for (int j = 0; j < 4; j++) {
            int n = base + j;
            float2 sv = *(const float2*)&g_S[n * H + 2 * lane];
            buf[j * 128 + 2 * lane] = sv.x;
            buf[j * 128 + 2 * lane + 1] = sv.y;
            cnt[j] = g_cnt[n];
        }
        __syncwarp();
        float bb0 = sB2[2 * lane], bb1 = sB2[2 * lane + 1];
        float u0[4], u1v[4];
#pragma unroll
        for (int j = 0; j < 4; j++) { u0[j] = cnt[j] * bb0; u1v[j] = cnt[j] * bb1; }
#pragma unroll 8
        for (int i = 0; i < H; i++) {
            float2 wv = *(const float2*)&sW2[i * H + 2 * lane];
#pragma unroll
            for (int j = 0; j < 4; j++) {
                float v = buf[j * 128 + i];
                u0[j] = fmaf(v, wv.x, u0[j]);
                u1v[j] = fmaf(v, wv.y, u1v[j]);
            }
        }
        __syncwarp();
        // phase 2: t = relu([h, upd] @ U1 + ub1)
#pragma unroll
        for (int j = 0; j < 4; j++) {
            int n = base + j;
            float2 hv = *(const float2*)&g_h[n * H + 2 * lane];
            buf[j * 128 + 2 * lane] = hv.x;
            buf[j * 128 + 2 * lane + 1] = hv.y;
            buf[j * 128 + H + 2 * lane] = u0[j];
            buf[j * 128 + H + 2 * lane + 1] = u1v[j];
        }
        __syncwarp();
        float tb0 = sUB1[2 * lane], tb1 = sUB1[2 * lane + 1];
        float t0[4], t1[4];
#pragma unroll
        for (int j = 0; j < 4; j++) { t0[j] = tb0; t1[j] = tb1; }
#pragma unroll 8
        for (int i = 0; i < 2 * H; i++) {
            float2 wv = *(const float2*)&sU1[i * H + 2 * lane];
#pragma unroll
            for (int j = 0; j < 4; j++) {
                float v = buf[j * 128 + i];
                t0[j] = fmaf(v, wv.x, t0[j]);
                t1[j] = fmaf(v, wv.y, t1[j]);
            }
        }
        __syncwarp();
        // phase 3: h = relu(relu(t) @ U2 + ub2)
#pragma unroll
        for (int j = 0; j < 4; j++) {
            buf[j * 128 + 2 * lane] = fmaxf(t0[j], 0.f);
            buf[j * 128 + 2 * lane + 1] = fmaxf(t1[j], 0.f);
        }
        __syncwarp();
        float zb0 = sUB2[2 * lane], zb1 = sUB2[2 * lane + 1];
        float z0[4], z1[4];
#pragma unroll
        for (int j = 0; j < 4; j++) { z0[j] = zb0; z1[j] = zb1; }
#pragma unroll 8
        for (int i = 0; i < H; i++) {
            float2 wv = *(const float2*)&sU2[i * H + 2 * lane];
#pragma unroll
            for (int j = 0; j < 4; j++) {
                float v = buf[j * 128 + i];
                z0[j] = fmaf(v, wv.x, z0[j]);
                z1[j] = fmaf(v, wv.y, z1[j]);
            }
        }
#pragma unroll
        for (int j = 0; j < 4; j++)
            *(float2*)&g_h[(base + j) * H + 2 * lane] =
                make_float2(fmaxf(z0[j], 0.f), fmaxf(z1[j], 0.f));
        __syncwarp();
    }
}

// ---------------------------------------------------------------------------
__global__ void k_final(const int* __restrict__ n2g, float* __restrict__ out) {
    int wid = threadIdx.x >> 5, lane = threadIdx.x & 31;
    int nwarps = (blockDim.x >> 5) * gridDim.x;
    int gw = blockIdx.x * (blockDim.x >> 5) + wid;
    for (int n = gw; n < NN; n += nwarps) {
        int g = n2g[n];
        float2 hv = *(const float2*)&g_h[n * H + 2 * lane];
        red_add_v2(&out[g * H + 2 * lane], hv.x, hv.y);
        *(float2*)&out[NG * H + n * H + 2 * lane] = hv;
    }
}

// ---------------------------------------------------------------------------
extern "C" void kernel_launch(void* const* d_in, const int* in_sizes, int n_in,
                              void* d_out, int out_size) {
    const float* x        = (const float*)d_in[0];
    const int*   el       = (const int*)d_in[1];
    const int*   nstruct  = (const int*)d_in[2];
    const float* ef       = (const float*)d_in[3];
    const float* ew       = (const float*)d_in[4];
    const int*   n2g      = (const int*)d_in[5];
    const float* lin_w    = (const float*)d_in[7];
    const float* lin_b    = (const float*)d_in[8];
    const float* msg_w1   = (const float*)d_in[9];
    const float* msg_b1   = (const float*)d_in[10];
    const float* msg_w2   = (const float*)d_in[11];
    const float* msg_b2   = (const float*)d_in[12];
    const float* upd_w1   = (const float*)d_in[13];
    const float* upd_b1   = (const float*)d_in[14];
    const float* upd_w2   = (const float*)d_in[15];
    const float* upd_b2   = (const float*)d_in[16];
    float* out = (float*)d_out;

    static const size_t UPD_SMEM = (16576 + 8 * 512) * sizeof(float);
    cudaFuncSetAttribute(k_upd, cudaFuncAttributeMaxDynamicSharedMemorySize,
                         (int)UPD_SMEM);

    const int TPB = 256;
    const int NODE_BLOCKS = 1184;
    const int EDGE_BLOCKS = 4096;

    k_zero<<<(NN + TPB - 1) / TPB, TPB>>>(out);
    k_cnt<<<(NE + TPB - 1) / TPB, TPB>>>(el, ew);
    k_h0<<<NODE_BLOCKS, TPB>>>(x, lin_w, lin_b);

    for (int l = 0; l < NL; l++) {
        const float* w1 = msg_w1 + (size_t)l * MSGIN * H;
        k_pq<<<NODE_BLOCKS, TPB>>>(w1, msg_b1 + l * H, nstruct);
        k_edge<<<EDGE_BLOCKS, TPB>>>(w1 + (2 * H + 2 * SCD) * H, el, ef, ew);
        k_upd<<<NODE_BLOCKS, TPB, UPD_SMEM>>>(
            msg_w2 + (size_t)l * H * H, msg_b2 + l * H,
            upd_w1 + (size_t)l * 2 * H * H, upd_b1 + l * H,
            upd_w2 + (size_t)l * H * H, upd_b2 + l * H);
    }

    k_final<<<NODE_BLOCKS, TPB>>>(n2g, out);
}